// round 1
// baseline (speedup 1.0000x reference)
#include <cuda_runtime.h>
#include <cstdint>

#define MAX_SEG 100001

// scratch (no cudaMalloc allowed)
__device__ int g_offsets[MAX_SEG + 1];
__device__ int g_is64;

// ---------------------------------------------------------------------------
// 1) dtype detection: reference declares int64 but JAX may emit int32.
//    If buffer is really int32, interpreting pairs as int64 yields values
//    >= 2^32 (unless the odd word is exactly 0), so checking 64 values
//    against [0, n_src) identifies the layout with certainty in practice.
// ---------------------------------------------------------------------------
__global__ void detect_kernel(const void* gidx, int n_src, int n_check) {
    if (blockIdx.x == 0 && threadIdx.x == 0) {
        const long long* p = (const long long*)gidx;
        int is64 = 1;
        for (int i = 0; i < n_check; i++) {
            long long v = p[i];
            if (v < 0 || v >= (long long)n_src) { is64 = 0; break; }
        }
        g_is64 = is64;
    }
}

__device__ __forceinline__ long long load_idx(const void* p, int i, bool is64) {
    return is64 ? ((const long long*)p)[i] : (long long)((const int*)p)[i];
}

// ---------------------------------------------------------------------------
// 2) CSR offsets from sorted segment ids. offsets[s] = first edge with
//    seg >= s. Boundary threads fill (prev, cur]; thread 0 fills [0, seg0];
//    thread E-1 fills the tail (seg[E-1], nseg].
// ---------------------------------------------------------------------------
__global__ void build_offsets_kernel(const void* seg, int E, int nseg) {
    int e = blockIdx.x * blockDim.x + threadIdx.x;
    if (e >= E) return;
    bool is64 = (g_is64 != 0);
    int cur = (int)load_idx(seg, e, is64);
    int prev = (e == 0) ? -1 : (int)load_idx(seg, e - 1, is64);
    for (int s = prev + 1; s <= cur; s++) g_offsets[s] = e;
    if (e == E - 1) {
        for (int s = cur + 1; s <= nseg; s++) g_offsets[s] = E;
    }
}

// ---------------------------------------------------------------------------
// 3) one warp per segment: gather rows, accumulate, write mean.
//    lane owns 2 dims -> float2, 256B coalesced row read per edge.
//    unroll x4 for 4 independent idx->row load chains (MLP).
// ---------------------------------------------------------------------------
__global__ void seg_mean_kernel(const float* __restrict__ values,
                                const void* __restrict__ gidx,
                                float* __restrict__ out, int nseg) {
    int warp = (blockIdx.x * blockDim.x + threadIdx.x) >> 5;
    int lane = threadIdx.x & 31;
    if (warp >= nseg) return;

    const bool is64 = (g_is64 != 0);
    int start = g_offsets[warp];
    int end   = g_offsets[warp + 1];

    float2 a0 = {0.f, 0.f}, a1 = {0.f, 0.f}, a2 = {0.f, 0.f}, a3 = {0.f, 0.f};

    int e = start;
    for (; e + 4 <= end; e += 4) {
        long long i0 = load_idx(gidx, e + 0, is64);
        long long i1 = load_idx(gidx, e + 1, is64);
        long long i2 = load_idx(gidx, e + 2, is64);
        long long i3 = load_idx(gidx, e + 3, is64);
        float2 v0 = ((const float2*)(values + i0 * 64))[lane];
        float2 v1 = ((const float2*)(values + i1 * 64))[lane];
        float2 v2 = ((const float2*)(values + i2 * 64))[lane];
        float2 v3 = ((const float2*)(values + i3 * 64))[lane];
        a0.x += v0.x; a0.y += v0.y;
        a1.x += v1.x; a1.y += v1.y;
        a2.x += v2.x; a2.y += v2.y;
        a3.x += v3.x; a3.y += v3.y;
    }
    for (; e < end; e++) {
        long long i0 = load_idx(gidx, e, is64);
        float2 v0 = ((const float2*)(values + i0 * 64))[lane];
        a0.x += v0.x; a0.y += v0.y;
    }

    float sx = (a0.x + a1.x) + (a2.x + a3.x);
    float sy = (a0.y + a1.y) + (a2.y + a3.y);

    int cnt = end - start;
    float inv = 1.0f / (float)(cnt > 0 ? cnt : 1);
    float2 r = {sx * inv, sy * inv};
    ((float2*)(out + (long long)warp * 64))[lane] = r;
}

// ---------------------------------------------------------------------------
// launch
// inputs: 0=values [N_SRC,64] f32, 1=gather_idx [E] i64/i32,
//         2=segment_ids [E] i64/i32 (sorted), 3=num_segments (unused scalar)
// out: [nseg,64] f32, nseg = out_size/64
// ---------------------------------------------------------------------------
extern "C" void kernel_launch(void* const* d_in, const int* in_sizes, int n_in,
                              void* d_out, int out_size) {
    const float* values = (const float*)d_in[0];
    const void*  gidx   = d_in[1];
    const void*  seg    = d_in[2];
    float* out = (float*)d_out;

    int n_src = in_sizes[0] / 64;
    int E     = in_sizes[1];
    int nseg  = out_size / 64;
    if (nseg > MAX_SEG) nseg = MAX_SEG;

    int n_check = E >= 64 ? 64 : E;
    detect_kernel<<<1, 32>>>(gidx, n_src, n_check);

    int threads = 256;
    build_offsets_kernel<<<(E + threads - 1) / threads, threads>>>(seg, E, nseg);

    int warps_per_block = threads / 32;
    int blocks = (nseg + warps_per_block - 1) / warps_per_block;
    seg_mean_kernel<<<blocks, threads>>>(values, gidx, out, nseg);
}